// round 2
// baseline (speedup 1.0000x reference)
#include <cuda_runtime.h>
#include <cstdint>

// Depthwise 3D conv, 3x3x3, SAME, stride 1.
// x: (N=4, D=16, H=112, W=112, C=64) f32, NDHWC
// w: (3,3,3,1,64) f32
// out[n,d,h,w,c] = sum_{kd,kh,kw} x[n,d+kd-1,h+kh-1,w+kw-1,c] * w[kd,kh,kw,0,c]
//
// Strategy: register-blocked 4(H) x 4(W) x 4(C) output tile per thread.
// Channels vectorized as float4 (LDG.128 / STG.128), math via packed
// fma.rn.f32x2 (FFMA2) to halve FMA instruction count.

#define C_TOT   64
#define C4      16          // float4 channel groups
#define W_DIM   112
#define H_DIM   112
#define D_DIM   16
#define N_DIM   4
#define HS      4
#define WS      4
#define WT      (W_DIM / WS)   // 28
#define HT      (H_DIM / HS)   // 28
#define TILES   (WT * HT)      // 784
#define TPB_TILES 8            // tiles per block
#define TPB     (TPB_TILES * C4)  // 128 threads

__device__ __forceinline__ void fma2(unsigned long long& d,
                                     unsigned long long a,
                                     unsigned long long b) {
    asm("fma.rn.f32x2 %0, %1, %2, %0;" : "+l"(d) : "l"(a), "l"(b));
}

__global__ void __launch_bounds__(TPB)
dwconv3d_kernel(const ulonglong2* __restrict__ xin,
                const ulonglong2* __restrict__ win,
                ulonglong2* __restrict__ out)
{
    const int tx   = threadIdx.x;
    const int c4   = tx & (C4 - 1);
    const int tile = blockIdx.x * TPB_TILES + (tx >> 4);   // 0..783
    const int ht   = tile / WT;
    const int wt   = tile - ht * WT;
    const int d    = blockIdx.y;
    const int n    = blockIdx.z;
    const int h0   = ht * HS;
    const int w0   = wt * WS;

    ulonglong2 acc[HS][WS];
    #pragma unroll
    for (int i = 0; i < HS; i++)
        #pragma unroll
        for (int j = 0; j < WS; j++)
            acc[i][j] = make_ulonglong2(0ull, 0ull);

    const ulonglong2 zero2 = make_ulonglong2(0ull, 0ull);

    #pragma unroll
    for (int kd = 0; kd < 3; kd++) {
        const int id = d + kd - 1;
        if (id < 0 || id >= D_DIM) continue;

        // weights for this kd-plane: 9 float4 in registers (L1-resident loads)
        ulonglong2 wgt[3][3];
        #pragma unroll
        for (int kh = 0; kh < 3; kh++)
            #pragma unroll
            for (int kw = 0; kw < 3; kw++)
                wgt[kh][kw] = win[((kd * 3 + kh) * 3 + kw) * C4 + c4];

        const size_t slice = ((size_t)(n * D_DIM + id)) * H_DIM;

        #pragma unroll
        for (int r = 0; r < HS + 2; r++) {
            const int ih = h0 + r - 1;
            const bool hv = (ih >= 0) && (ih < H_DIM);

            ulonglong2 row[WS + 2];
            #pragma unroll
            for (int j = 0; j < WS + 2; j++) {
                const int iw = w0 + j - 1;
                const bool v = hv && (iw >= 0) && (iw < W_DIM);
                row[j] = v ? xin[((slice + ih) * W_DIM + iw) * C4 + c4] : zero2;
            }

            #pragma unroll
            for (int kh = 0; kh < 3; kh++) {
                const int oh = r - kh;     // output row fed by this input row
                if (oh >= 0 && oh < HS) {
                    #pragma unroll
                    for (int ow = 0; ow < WS; ow++) {
                        #pragma unroll
                        for (int kw = 0; kw < 3; kw++) {
                            fma2(acc[oh][ow].x, row[ow + kw].x, wgt[kh][kw].x);
                            fma2(acc[oh][ow].y, row[ow + kw].y, wgt[kh][kw].y);
                        }
                    }
                }
            }
        }
    }

    const size_t obase = ((size_t)(n * D_DIM + d)) * H_DIM;
    #pragma unroll
    for (int i = 0; i < HS; i++) {
        const size_t orow = ((obase + h0 + i) * W_DIM + w0) * C4 + c4;
        #pragma unroll
        for (int j = 0; j < WS; j++)
            out[orow + (size_t)j * C4] = acc[i][j];
    }
}

extern "C" void kernel_launch(void* const* d_in, const int* in_sizes, int n_in,
                              void* d_out, int out_size) {
    const ulonglong2* x = (const ulonglong2*)d_in[0];
    const ulonglong2* w = (const ulonglong2*)d_in[1];
    ulonglong2* o = (ulonglong2*)d_out;

    dim3 grid(TILES / TPB_TILES, D_DIM, N_DIM);   // (98, 16, 4)
    dwconv3d_kernel<<<grid, TPB>>>(x, w, o);
}

// round 3
// speedup vs baseline: 1.0513x; 1.0513x over previous
#include <cuda_runtime.h>
#include <cstdint>

// Depthwise 3D conv, 3x3x3, SAME, stride 1.
// x: (N=4, D=16, H=112, W=112, C=64) f32, NDHWC ; w: (3,3,3,1,64) f32
//
// R2: 2(H) x 4(W) x 4(C) register tile per thread, __launch_bounds__(128,4)
// to force 4 CTAs/SM (16 warps) for latency hiding. Pointer-based addressing
// with compile-time byte offsets to cut ALU work. Packed fma.rn.f32x2.

#define C4      16             // float4 channel groups per pixel
#define W_DIM   112
#define H_DIM   112
#define D_DIM   16
#define N_DIM   4
#define HS      2
#define WS      4
#define WT      (W_DIM / WS)   // 28
#define HT      (H_DIM / HS)   // 56
#define TILES   (WT * HT)      // 1568
#define TPB_TILES 8
#define TPB     (TPB_TILES * C4)   // 128 threads

#define ROW_STRIDE (W_DIM * C4)            // 1792 float4 per H-row
#define SLICE_STRIDE (H_DIM * W_DIM * C4)  // per D-slice

__device__ __forceinline__ void fma2(unsigned long long& d,
                                     unsigned long long a,
                                     unsigned long long b) {
    asm("fma.rn.f32x2 %0, %1, %2, %0;" : "+l"(d) : "l"(a), "l"(b));
}

__global__ void __launch_bounds__(TPB, 4)
dwconv3d_kernel(const ulonglong2* __restrict__ xin,
                const ulonglong2* __restrict__ win,
                ulonglong2* __restrict__ out)
{
    const int tx   = threadIdx.x;
    const int c4   = tx & (C4 - 1);
    const int tile = blockIdx.x * TPB_TILES + (tx >> 4);   // 0..1567
    const int ht   = tile / WT;
    const int wt   = tile - ht * WT;
    const int d    = blockIdx.y;
    const int n    = blockIdx.z;
    const int h0   = ht * HS;
    const int w0   = wt * WS;

    const bool lv = (wt != 0);          // left halo column valid
    const bool rv = (wt != WT - 1);     // right halo column valid

    // base pointer at (n, *, h=0, w=w0-1, c4)
    const ulonglong2* xn = xin
        + (size_t)n * (D_DIM * (size_t)SLICE_STRIDE)
        + (ptrdiff_t)(w0 - 1) * C4 + c4;
    const ulonglong2* wb = win + c4;

    ulonglong2 acc[HS][WS];
    #pragma unroll
    for (int i = 0; i < HS; i++)
        #pragma unroll
        for (int j = 0; j < WS; j++)
            acc[i][j] = make_ulonglong2(0ull, 0ull);

    const ulonglong2 zero2 = make_ulonglong2(0ull, 0ull);

    #pragma unroll
    for (int kd = 0; kd < 3; kd++) {
        const int id = d + kd - 1;
        if (id < 0 || id >= D_DIM) continue;

        // 9 weight float4 for this kd plane, constant offsets from wb
        ulonglong2 wgt[3][3];
        #pragma unroll
        for (int kh = 0; kh < 3; kh++)
            #pragma unroll
            for (int kw = 0; kw < 3; kw++)
                wgt[kh][kw] = wb[((kd * 3 + kh) * 3 + kw) * C4];

        const ulonglong2* xd = xn + (size_t)id * SLICE_STRIDE;

        #pragma unroll
        for (int r = 0; r < HS + 2; r++) {
            const int ih = h0 + r - 1;
            const bool hv = (ih >= 0) && (ih < H_DIM);
            const ulonglong2* p = xd + (ptrdiff_t)ih * ROW_STRIDE;

            ulonglong2 row[WS + 2];
            row[0] = (hv && lv) ? p[0] : zero2;
            #pragma unroll
            for (int j = 1; j <= WS; j++)
                row[j] = hv ? p[j * C4] : zero2;
            row[WS + 1] = (hv && rv) ? p[(WS + 1) * C4] : zero2;

            #pragma unroll
            for (int kh = 0; kh < 3; kh++) {
                const int oh = r - kh;
                if (oh >= 0 && oh < HS) {
                    #pragma unroll
                    for (int ow = 0; ow < WS; ow++) {
                        #pragma unroll
                        for (int kw = 0; kw < 3; kw++) {
                            fma2(acc[oh][ow].x, row[ow + kw].x, wgt[kh][kw].x);
                            fma2(acc[oh][ow].y, row[ow + kw].y, wgt[kh][kw].y);
                        }
                    }
                }
            }
        }
    }

    ulonglong2* o = out
        + (((size_t)(n * D_DIM + d) * H_DIM + h0) * W_DIM + w0) * C4 + c4;
    #pragma unroll
    for (int i = 0; i < HS; i++)
        #pragma unroll
        for (int j = 0; j < WS; j++)
            o[i * ROW_STRIDE + j * C4] = acc[i][j];
}

extern "C" void kernel_launch(void* const* d_in, const int* in_sizes, int n_in,
                              void* d_out, int out_size) {
    const ulonglong2* x = (const ulonglong2*)d_in[0];
    const ulonglong2* w = (const ulonglong2*)d_in[1];
    ulonglong2* o = (ulonglong2*)d_out;

    dim3 grid(TILES / TPB_TILES, D_DIM, N_DIM);   // (196, 16, 4)
    dwconv3d_kernel<<<grid, TPB>>>(x, w, o);
}